// round 16
// baseline (speedup 1.0000x reference)
#include <cuda_runtime.h>
#include <cstdint>

#define BSZ 4
#define LM  256
#define LE  512
#define HD  512
#define VOC 32000

#define STAGES 3
#define TILEF  2304      // floats per A or B stage buffer (64*36 or 32*72)
#define GSMEM  (STAGES * 2 * TILEF * 4)   // 55296 B dynamic smem per GEMM block

// zero-fill slices (in float4 units) carried by the three GEMM kernels
#define N4_TOTAL 8192000L                 // BSZ*LM*VOC/4
#define ZG_PER   32000                    // k_G: 64 blocks  -> 2,048,000 f4
#define ZT_PER   24000                    // k_T: 128 blocks -> 3,072,000 f4
#define ZL_PER   24000                    // k_log: 128 blocks -> 3,072,000 f4
#define ZT_BASE  2048000L
#define ZL_BASE  5120000L

// Scratch (device globals; no allocation allowed in kernel_launch)
__device__ float g_G[HD * HD];               // Wm @ We^T * scale    (1 MB)
__device__ float g_T[BSZ * LM * HD];         // M @ G                (2 MB)
__device__ float g_log[BSZ * LM * LE];       // logits               (2 MB)

// ---------------------------------------------------------------------------
// Coalesced zero-fill of a per-block slice of the output. Plain stores
// (evict-normal) so the lines stay L2-resident for the patch atomics.
// ---------------------------------------------------------------------------
__device__ __forceinline__ void zero_slice(float4* p, long base, int perBlock,
                                           int blockLin)
{
    long b0 = base + (long)blockLin * perBlock;
    float4 z = make_float4(0.f, 0.f, 0.f, 0.f);
    for (int j = threadIdx.x; j < perBlock; j += 256)
        p[b0 + j] = z;
}

// ---------------------------------------------------------------------------
// tf32 tensor-core GEMM core: 64x64 tile, 256 threads (4x2 warps of 16x32),
// BK=32, 3-stage cp.async pipeline, mma.sync.m16n8k8.tf32.
// TB=true:  C[m,n] = alpha * sum_k A[m,k] * B[n,k]   (NT, both K-major)
// TB=false: C[m,n] = alpha * sum_k A[m,k] * B[k,n]   (NN)
// ---------------------------------------------------------------------------
__device__ __forceinline__ void cp16(void* dst, const void* src)
{
    uint32_t d = (uint32_t)__cvta_generic_to_shared(dst);
    asm volatile("cp.async.cg.shared.global [%0], [%1], 16;\n"
                 :: "r"(d), "l"(src));
}
__device__ __forceinline__ void cp_commit()
{
    asm volatile("cp.async.commit_group;\n" ::: "memory");
}
__device__ __forceinline__ void cp_wait0()
{
    asm volatile("cp.async.wait_group 0;\n" ::: "memory");
}
__device__ __forceinline__ void cp_wait1()
{
    asm volatile("cp.async.wait_group 1;\n" ::: "memory");
}
__device__ __forceinline__ void mma_tf32(float* d, const uint32_t* a,
                                         const uint32_t* b)
{
    asm volatile(
        "mma.sync.aligned.m16n8k8.row.col.f32.tf32.tf32.f32 "
        "{%0,%1,%2,%3}, {%4,%5,%6,%7}, {%8,%9}, {%0,%1,%2,%3};\n"
        : "+f"(d[0]), "+f"(d[1]), "+f"(d[2]), "+f"(d[3])
        : "r"(a[0]), "r"(a[1]), "r"(a[2]), "r"(a[3]),
          "r"(b[0]), "r"(b[1]));
}

#define PA 36   // smem pitch, K-major tiles (banks 4*gid+tig: conflict-free)
#define PB 72   // smem pitch, NN B tile     (banks 8*tig+gid: conflict-free)

template <bool TB>
__device__ __forceinline__ void gemm_core(
    const float* __restrict__ A, const float* __restrict__ B,
    float* __restrict__ C, int lda, int ldb, int ldc,
    int m0, int n0, int kLen, float alpha, float* smem)
{
    float (*As)[TILEF] = reinterpret_cast<float(*)[TILEF]>(smem);
    float (*Bs)[TILEF] = reinterpret_cast<float(*)[TILEF]>(smem
                                                           + STAGES * TILEF);

    const int tid  = threadIdx.x;
    const int lane = tid & 31, w = tid >> 5;
    const int gid = lane >> 2, tig = lane & 3;
    const int wm = (w & 3) * 16, wn = (w >> 2) * 32;

    const int NK = kLen / 32;

    auto loadA = [&](int st, int kt) {
        int k0 = kt * 32;
#pragma unroll
        for (int i = 0; i < 2; i++) {
            int id = tid + i * 256;
            int row = id >> 3, cc = id & 7;
            cp16(&As[st][row * PA + cc * 4],
                 A + (long)(m0 + row) * lda + k0 + cc * 4);
        }
    };
    auto loadB = [&](int st, int kt) {
        int k0 = kt * 32;
        if (TB) {
#pragma unroll
            for (int i = 0; i < 2; i++) {
                int id = tid + i * 256;
                int row = id >> 3, cc = id & 7;
                cp16(&Bs[st][row * PA + cc * 4],
                     B + (long)(n0 + row) * ldb + k0 + cc * 4);
            }
        } else {
#pragma unroll
            for (int i = 0; i < 2; i++) {
                int id = tid + i * 256;
                int row = id >> 4, cc = id & 15;
                cp16(&Bs[st][row * PB + cc * 4],
                     B + (long)(k0 + row) * ldb + n0 + cc * 4);
            }
        }
    };

    float acc[4][4] = {};

    // prologue: 2 stages in flight
    loadA(0, 0); loadB(0, 0); cp_commit();
    if (NK > 1) { loadA(1, 1); loadB(1, 1); cp_commit(); }

    int buf = 0;        // stage being consumed this iter
    int ls  = 2;        // stage the next prefetch writes into
    for (int kt = 0; kt < NK; kt++) {
        if (kt < NK - 1) cp_wait1(); else cp_wait0();
        __syncthreads();
        if (kt + 2 < NK) {
            loadA(ls, kt + 2);
            loadB(ls, kt + 2);
            cp_commit();
            ls = (ls == STAGES - 1) ? 0 : ls + 1;
        }
#pragma unroll
        for (int ks = 0; ks < 4; ks++) {
            const int kk = ks * 8;
            uint32_t a[4];
            {
                int rb = wm + gid;
                a[0] = __float_as_uint(As[buf][(rb)     * PA + kk + tig]);
                a[1] = __float_as_uint(As[buf][(rb + 8) * PA + kk + tig]);
                a[2] = __float_as_uint(As[buf][(rb)     * PA + kk + tig + 4]);
                a[3] = __float_as_uint(As[buf][(rb + 8) * PA + kk + tig + 4]);
            }
            uint32_t b[4][2];
#pragma unroll
            for (int nj = 0; nj < 4; nj++) {
                int cb = wn + nj * 8 + gid;
                if (TB) {
                    b[nj][0] = __float_as_uint(Bs[buf][cb * PA + kk + tig]);
                    b[nj][1] = __float_as_uint(Bs[buf][cb * PA + kk + tig + 4]);
                } else {
                    b[nj][0] = __float_as_uint(Bs[buf][(kk + tig)     * PB + cb]);
                    b[nj][1] = __float_as_uint(Bs[buf][(kk + tig + 4) * PB + cb]);
                }
            }
#pragma unroll
            for (int nj = 0; nj < 4; nj++)
                mma_tf32(acc[nj], a, b[nj]);
        }
        buf = (buf == STAGES - 1) ? 0 : buf + 1;
    }

#pragma unroll
    for (int nj = 0; nj < 4; nj++) {
        int r0 = m0 + wm + gid;
        int c0 = n0 + wn + nj * 8 + 2 * tig;
        C[(long)r0 * ldc + c0]           = acc[nj][0] * alpha;
        C[(long)r0 * ldc + c0 + 1]       = acc[nj][1] * alpha;
        C[(long)(r0 + 8) * ldc + c0]     = acc[nj][2] * alpha;
        C[(long)(r0 + 8) * ldc + c0 + 1] = acc[nj][3] * alpha;
    }
}

// ---------------------------------------------------------------------------
// G = Wm @ We^T * scale (NT, full K) + zero-fill slice of out. grid (8, 8).
// ---------------------------------------------------------------------------
__global__ __launch_bounds__(256) void k_G(
    const float* __restrict__ Wm, const float* __restrict__ We,
    float* __restrict__ G, float scale, float4* __restrict__ outz)
{
    extern __shared__ float smem[];
    zero_slice(outz, 0L, ZG_PER, blockIdx.y * 8 + blockIdx.x);
    gemm_core<true>(Wm, We, G, HD, HD, HD,
                    blockIdx.y * 64, blockIdx.x * 64, HD, scale, smem);
}

// ---------------------------------------------------------------------------
// T = M_flat @ G (NN, full K) + zero-fill slice of out. grid (8, 16).
// ---------------------------------------------------------------------------
__global__ __launch_bounds__(256) void k_T(
    const float* __restrict__ M, const float* __restrict__ G,
    float* __restrict__ T, float4* __restrict__ outz)
{
    extern __shared__ float smem[];
    zero_slice(outz, ZT_BASE, ZT_PER, blockIdx.y * 8 + blockIdx.x);
    gemm_core<false>(M, G, T, HD, HD, HD,
                     blockIdx.y * 64, blockIdx.x * 64, HD, 1.f, smem);
}

// ---------------------------------------------------------------------------
// logits[b] = T[b] @ E[b]^T (NT, full K) + zero-fill slice. grid (8, 4, BSZ).
// ---------------------------------------------------------------------------
__global__ __launch_bounds__(256) void k_log(
    const float* __restrict__ T, const float* __restrict__ E,
    float* __restrict__ logs, float4* __restrict__ outz)
{
    extern __shared__ float smem[];
    int b = blockIdx.z;
    zero_slice(outz, ZL_BASE, ZL_PER,
               (b * 4 + blockIdx.y) * 8 + blockIdx.x);
    const float* A = T + (long)b * LM * HD;
    const float* B = E + (long)b * LE * HD;
    float* C = logs + (long)b * LM * LE;
    gemm_core<true>(A, B, C, HD, HD, LE,
                    blockIdx.y * 64, blockIdx.x * 64, HD, 1.f, smem);
}

// ---------------------------------------------------------------------------
// Block reduction for 256 threads (8 warps). red8 is an 8-float smem array.
// ---------------------------------------------------------------------------
__device__ __forceinline__ float bred256(float v, bool mx, float* red8,
                                         int lane, int w)
{
#pragma unroll
    for (int o = 16; o > 0; o >>= 1) {
        float u = __shfl_xor_sync(0xffffffffu, v, o);
        v = mx ? fmaxf(v, u) : v + u;
    }
    if (lane == 0) red8[w] = v;
    __syncthreads();
    float x = red8[lane & 7];
#pragma unroll
    for (int o = 4; o > 0; o >>= 1) {
        float u = __shfl_xor_sync(0xffffffffu, x, o);
        x = mx ? fmaxf(x, u) : x + u;
    }
    __syncthreads();   // red8 free for next use
    return x;          // identical in every thread
}

// ---------------------------------------------------------------------------
// Patch kernel: one block per row (1024 blocks, 256 threads, tiny smem).
// lambda + dual softmax (identical math to before), then 512 direct global
// atomicAdd into the pre-zeroed (L2-dirty) output row. No 32 KB smem tile,
// no 8000-float store stream -- the 131 MB zero-fill already happened inside
// the GEMM kernels and its DRAM writeback overlapped them.
// ---------------------------------------------------------------------------
__global__ __launch_bounds__(256) void k_patch(
    const int* __restrict__ idx, const float* __restrict__ bq,
    const float* __restrict__ bc, const float* __restrict__ D,
    const float* __restrict__ Cq, const float* __restrict__ Cc,
    const float* __restrict__ Wl, const float* __restrict__ bl,
    const float* __restrict__ logs, float* __restrict__ out)
{
    __shared__ float red8[8];

    const int r = blockIdx.x;                // 0 .. BSZ*LM-1
    const int b = r >> 8;                    // r / LM
    const int t = threadIdx.x, lane = t & 31, w = t >> 5;

    // lambda (256 threads x 2 elements of each of the 3 chunks)
    const float* dr  = D  + (long)r * HD;
    const float* cqr = Cq + (long)r * HD;
    const float* ccr = Cc + (long)r * HD;
    float s = 0.f;
#pragma unroll
    for (int i = 0; i < 2; i++) {
        int j = t + i * 256;
        s += dr[j] * Wl[j] + cqr[j] * Wl[HD + j] + ccr[j] * Wl[2 * HD + j];
    }
    s = bred256(s, false, red8, lane, w);
    float lam = 1.f / (1.f + __expf(-(s + bl[0])));

    // logits: 2 elements per thread (LE == 512)
    float vq[2], vc[2];
#pragma unroll
    for (int i = 0; i < 2; i++) {
        int e = t + i * 256;
        float l = logs[(long)r * LE + e];
        vq[i] = l + bq[b * LE + e];
        vc[i] = l + bc[b * LE + e];
    }

    float mq = bred256(fmaxf(vq[0], vq[1]), true, red8, lane, w);
    float mc = bred256(fmaxf(vc[0], vc[1]), true, red8, lane, w);
    float eq[2], ec[2];
    eq[0] = __expf(vq[0] - mq); eq[1] = __expf(vq[1] - mq);
    ec[0] = __expf(vc[0] - mc); ec[1] = __expf(vc[1] - mc);
    float sq = bred256(eq[0] + eq[1], false, red8, lane, w);
    float sc = bred256(ec[0] + ec[1], false, red8, lane, w);

    float iq = lam / sq, ic = (1.f - lam) / sc;

    float* orow = out + (long)r * VOC;
#pragma unroll
    for (int i = 0; i < 2; i++) {
        int e = t + i * 256;
        atomicAdd(orow + idx[b * LE + e], eq[i] * iq + ec[i] * ic);
    }
}

// ---------------------------------------------------------------------------
extern "C" void kernel_launch(void* const* d_in, const int* in_sizes, int n_in,
                              void* d_out, int out_size)
{
    const int*   inputs = (const int*)  d_in[0];
    const float* D      = (const float*)d_in[1];
    const float* Cq     = (const float*)d_in[2];
    const float* Cc     = (const float*)d_in[3];
    const float* Mi     = (const float*)d_in[4];
    const float* E      = (const float*)d_in[5];
    const float* bq     = (const float*)d_in[6];
    const float* bc     = (const float*)d_in[7];
    const float* Wl     = (const float*)d_in[8];
    const float* bl     = (const float*)d_in[9];
    const float* We     = (const float*)d_in[10];
    const float* Wm     = (const float*)d_in[11];
    float* out = (float*)d_out;

    float *gG, *gT, *gL;
    cudaGetSymbolAddress((void**)&gG, g_G);
    cudaGetSymbolAddress((void**)&gT, g_T);
    cudaGetSymbolAddress((void**)&gL, g_log);

    static bool init = false;
    if (!init) {
        cudaFuncSetAttribute(k_G,
                             cudaFuncAttributeMaxDynamicSharedMemorySize,
                             GSMEM);
        cudaFuncSetAttribute(k_T,
                             cudaFuncAttributeMaxDynamicSharedMemorySize,
                             GSMEM);
        cudaFuncSetAttribute(k_log,
                             cudaFuncAttributeMaxDynamicSharedMemorySize,
                             GSMEM);
        init = true;
    }

    const float scale = 0.044194173824159216f;  // 512^-0.5
    float4* outz = (float4*)out;

    // G = Wm @ We^T * scale + zero out[0 : 32MB)        (64 blocks)
    k_G<<<dim3(8, 8), 256, GSMEM>>>(Wm, We, gG, scale, outz);
    // T = M_flat @ G + zero out[32MB : 81MB)            (128 blocks)
    k_T<<<dim3(8, 16), 256, GSMEM>>>(Mi, gG, gT, outz);
    // logits + zero out[81MB : 131MB)                   (128 blocks)
    k_log<<<dim3(8, 4, BSZ), 256, GSMEM>>>(gT, E, gL, outz);
    // lambda + softmax + sparse atomic patch into the zeroed output
    k_patch<<<BSZ * LM, 256>>>(inputs, bq, bc, D, Cq, Cc, Wl, bl, gL, out);
}